// round 15
// baseline (speedup 1.0000x reference)
#include <cuda_runtime.h>
#include <cuda_bf16.h>
#include <math.h>
#include <cstdint>

#define Bb   2
#define LL   1024
#define DD   1024
#define HH   16
#define HDp  64
#define MM   (Bb * LL)
#define NE   (2 * LL - 1)   // 2047

typedef __nv_bfloat16 bf16;

// Scratch (allocation-free rule: device globals)
__device__ bf16 g_xhi[MM * DD],  g_xlo[MM * DD];
__device__ bf16 g_wqh[DD * DD],  g_wql[DD * DD];
__device__ bf16 g_wkh[DD * DD],  g_wkl[DD * DD];
__device__ bf16 g_wvh[DD * DD],  g_wvl[DD * DD];
__device__ bf16 g_woh[DD * DD],  g_wol[DD * DD];
__device__ bf16 g_qhi[MM * DD],  g_qlo[MM * DD];
__device__ bf16 g_khi[MM * DD],  g_klo[MM * DD];
__device__ bf16 g_vhi[MM * DD],  g_vlo[MM * DD];
__device__ bf16 g_ehi[NE * HDp], g_elo[NE * HDp];
__device__ bf16 g_chi[MM * DD],  g_clo[MM * DD];

// ===========================================================================
// Helpers (sm_80+ ISA; proven on this toolchain)
// ===========================================================================
__device__ __forceinline__ uint32_t smem_u32(const void* p) {
    uint32_t a;
    asm("{ .reg .u64 t; cvta.to.shared.u64 t, %1; cvt.u32.u64 %0, t; }"
        : "=r"(a) : "l"(p));
    return a;
}
__device__ __forceinline__ void ldsm_x4(uint32_t addr, uint32_t r[4]) {
    asm volatile("ldmatrix.sync.aligned.m8n8.x4.shared.b16 {%0,%1,%2,%3}, [%4];"
                 : "=r"(r[0]), "=r"(r[1]), "=r"(r[2]), "=r"(r[3]) : "r"(addr));
}
__device__ __forceinline__ void ldsm_x4t(uint32_t addr, uint32_t r[4]) {
    asm volatile("ldmatrix.sync.aligned.m8n8.x4.trans.shared.b16 {%0,%1,%2,%3}, [%4];"
                 : "=r"(r[0]), "=r"(r[1]), "=r"(r[2]), "=r"(r[3]) : "r"(addr));
}
__device__ __forceinline__ void mma_bf16(float c[4], const uint32_t a[4],
                                         uint32_t b0, uint32_t b1) {
    asm volatile(
        "mma.sync.aligned.m16n8k16.row.col.f32.bf16.bf16.f32 "
        "{%0,%1,%2,%3}, {%4,%5,%6,%7}, {%8,%9}, {%0,%1,%2,%3};"
        : "+f"(c[0]), "+f"(c[1]), "+f"(c[2]), "+f"(c[3])
        : "r"(a[0]), "r"(a[1]), "r"(a[2]), "r"(a[3]), "r"(b0), "r"(b1));
}
__device__ __forceinline__ void cp16(uint32_t dst, const void* src) {
    asm volatile("cp.async.ca.shared.global [%0], [%1], 16;"
                 :: "r"(dst), "l"(src));
}
__device__ __forceinline__ void cp16z(uint32_t dst, const void* src, bool pred) {
    int sz = pred ? 16 : 0;
    asm volatile("cp.async.ca.shared.global [%0], [%1], 16, %2;"
                 :: "r"(dst), "l"(src), "r"(sz));
}
#define CP_COMMIT() asm volatile("cp.async.commit_group;" ::: "memory")
#define CP_WAIT0()  asm volatile("cp.async.wait_group 0;" ::: "memory")
#define CP_WAIT1()  asm volatile("cp.async.wait_group 1;" ::: "memory")
#define CP_WAIT_ALL() do { CP_COMMIT(); CP_WAIT0(); } while (0)

__device__ __forceinline__ uint32_t pack2(bf16 a, bf16 b) {
    return (uint32_t)__bfloat16_as_ushort(a) | ((uint32_t)__bfloat16_as_ushort(b) << 16);
}
__device__ __forceinline__ void split_pair(float a, float b, uint32_t& hi, uint32_t& lo) {
    bf16 ha = __float2bfloat16(a), hb = __float2bfloat16(b);
    hi = pack2(ha, hb);
    lo = pack2(__float2bfloat16(a - __bfloat162float(ha)),
               __float2bfloat16(b - __bfloat162float(hb)));
}

// ===========================================================================
// fp32 -> bf16 hi/lo split, all tensors in ONE launch (segment dispatch)
// ===========================================================================
#define SEG0 (MM * DD)
#define SEG1 (SEG0 + DD * DD)
#define SEG2 (SEG1 + DD * DD)
#define SEG3 (SEG2 + DD * DD)
#define SEG4 (SEG3 + DD * DD)
#define SEG5 (SEG4 + NE * HDp)
#define CVT_BLOCKS ((SEG5 / 4 + 255) / 256)

__global__ void cvt_all_kernel(const float* __restrict__ x,  const float* __restrict__ Wq,
                               const float* __restrict__ Wk, const float* __restrict__ Wv,
                               const float* __restrict__ Wo, const float* __restrict__ E)
{
    int i = (blockIdx.x * 256 + threadIdx.x) * 4;
    if (i >= SEG5) return;
    const float* s; bf16 *hi, *lo; int off;
    if      (i < SEG0) { s = x;  hi = g_xhi; lo = g_xlo; off = i; }
    else if (i < SEG1) { s = Wq; hi = g_wqh; lo = g_wql; off = i - SEG0; }
    else if (i < SEG2) { s = Wk; hi = g_wkh; lo = g_wkl; off = i - SEG1; }
    else if (i < SEG3) { s = Wv; hi = g_wvh; lo = g_wvl; off = i - SEG2; }
    else if (i < SEG4) { s = Wo; hi = g_woh; lo = g_wol; off = i - SEG3; }
    else               { s = E;  hi = g_ehi; lo = g_elo; off = i - SEG4; }
    float4 v = *(const float4*)(s + off);
    uint32_t h0, l0, h1, l1;
    split_pair(v.x, v.y, h0, l0);
    split_pair(v.z, v.w, h1, l1);
    *(uint2*)(hi + off) = make_uint2(h0, h1);
    *(uint2*)(lo + off) = make_uint2(l0, l1);
}

// ===========================================================================
// Tensor-core GEMM: C = A(MxK) @ W(NxK)^T + bias, pre-split bf16 inputs.
// 128x128 CTA tile, 512 threads / 16 warps (4m x 4n), warp tile 32x32.
// K chunks of 64, 2-stage cp.async pipeline. Inner mma reordered in 3
// phases (hh, hl, lh) -> same-acc dependency distance 8 (was 1).
// Per-accumulator addition order unchanged (bit-identical numerics).
// ===========================================================================
#define GSA     144
#define GTILE_B (128 * GSA)
#define OFF_AHI 0
#define OFF_ALO GTILE_B
#define OFF_BHI (2 * GTILE_B)
#define OFF_BLO (3 * GTILE_B)
#define GBUF_B  (4 * GTILE_B)            // 73728 per stage
#define GEMM_SMEM (2 * GBUF_B)           // 147456

__global__ __launch_bounds__(512, 1)
void gemm_tc2_kernel(const bf16* __restrict__ ahi, const bf16* __restrict__ alo,
                     const bf16* __restrict__ w0h, const bf16* __restrict__ w0l,
                     const bf16* __restrict__ w1h, const bf16* __restrict__ w1l,
                     const bf16* __restrict__ w2h, const bf16* __restrict__ w2l,
                     const float* __restrict__ b0, const float* __restrict__ b1,
                     const float* __restrict__ b2,
                     bf16* c0h, bf16* c0l, bf16* c1h, bf16* c1l,
                     bf16* c2h, bf16* c2l,
                     float* cf, float scale0, int M, int N, int K)
{
    const int z = blockIdx.z;
    const bf16* wh   = (z == 0) ? w0h : (z == 1 ? w1h : w2h);
    const bf16* wl   = (z == 0) ? w0l : (z == 1 ? w1l : w2l);
    const float* bias = (z == 0) ? b0 : (z == 1 ? b1 : b2);
    bf16* chi = (z == 0) ? c0h : (z == 1 ? c1h : c2h);
    bf16* clo = (z == 0) ? c0l : (z == 1 ? c1l : c2l);
    const float scale = (z == 0) ? scale0 : 1.0f;

    extern __shared__ char sm[];
    const uint32_t sbase = smem_u32(sm);

    const int tid  = threadIdx.x;
    const int lane = tid & 31;
    const int wid  = tid >> 5;
    const int wm   = wid & 3;            // 0..3  (32 rows each)
    const int wn   = wid >> 2;           // 0..3  (32 cols each)
    const int bm   = blockIdx.y * 128;
    const int bn   = blockIdx.x * 128;

    float acc[2][4][4];
    #pragma unroll
    for (int i = 0; i < 2; i++)
        #pragma unroll
        for (int j = 0; j < 4; j++)
            #pragma unroll
            for (int r = 0; r < 4; r++) acc[i][j][r] = 0.f;

    const int frow = tid >> 2;
    const int fcol = (tid & 3) * 16;
    const bf16* pah = ahi + (size_t)(bm + frow) * K + fcol;
    const bf16* pal = alo + (size_t)(bm + frow) * K + fcol;
    const bf16* pwh = wh  + (size_t)(bn + frow) * K + fcol;
    const bf16* pwl = wl  + (size_t)(bn + frow) * K + fcol;
    const uint32_t dstrow = (uint32_t)(frow * GSA + fcol * 2);

    const int lr   = lane & 15;
    const int lc16 = (lane >> 4) * 16;
    const uint32_t a_rel = (uint32_t)((wm * 32 + lr) * GSA + lc16);
    const uint32_t b_rel = (uint32_t)((wn * 32 + lr) * GSA + lc16);

    // prologue: issue chunk 0 into buffer 0
    {
        const uint32_t d = sbase + dstrow;
        #pragma unroll
        for (int g = 0; g < 2; g++) {
            cp16(d + OFF_AHI + g * 16, pah + g * 8);
            cp16(d + OFF_ALO + g * 16, pal + g * 8);
            cp16(d + OFF_BHI + g * 16, pwh + g * 8);
            cp16(d + OFF_BLO + g * 16, pwl + g * 8);
        }
        CP_COMMIT();
    }

    const int NCH = K / 64;
    for (int c = 0; c < NCH; c++) {
        if (c + 1 < NCH) {
            const int kb = (c + 1) * 64;
            const uint32_t d = sbase + ((c + 1) & 1) * GBUF_B + dstrow;
            #pragma unroll
            for (int g = 0; g < 2; g++) {
                cp16(d + OFF_AHI + g * 16, pah + kb + g * 8);
                cp16(d + OFF_ALO + g * 16, pal + kb + g * 8);
                cp16(d + OFF_BHI + g * 16, pwh + kb + g * 8);
                cp16(d + OFF_BLO + g * 16, pwl + kb + g * 8);
            }
            CP_COMMIT();
            CP_WAIT1();      // chunk c complete (c+1 still in flight)
        } else {
            CP_WAIT0();
        }
        __syncthreads();     // chunk c visible to all warps

        const uint32_t a_lane = sbase + (c & 1) * GBUF_B + a_rel;
        const uint32_t b_lane = sbase + (c & 1) * GBUF_B + b_rel;
        #pragma unroll
        for (int ks = 0; ks < 4; ks++) {
            const uint32_t cb = (uint32_t)(ks * 32);
            uint32_t ah[2][4], al[2][4];
            #pragma unroll
            for (int mi = 0; mi < 2; mi++) {
                ldsm_x4(a_lane + OFF_AHI + mi * (16 * GSA) + cb, ah[mi]);
                ldsm_x4(a_lane + OFF_ALO + mi * (16 * GSA) + cb, al[mi]);
            }
            uint32_t bh[2][4], bl[2][4];
            #pragma unroll
            for (int nb = 0; nb < 2; nb++) {
                ldsm_x4(b_lane + OFF_BHI + nb * (16 * GSA) + cb, bh[nb]);
                ldsm_x4(b_lane + OFF_BLO + nb * (16 * GSA) + cb, bl[nb]);
            }
            // phase 1: hi x hi (8 independent mma)
            #pragma unroll
            for (int mi = 0; mi < 2; mi++)
                #pragma unroll
                for (int nb = 0; nb < 2; nb++) {
                    mma_bf16(acc[mi][2*nb],   ah[mi], bh[nb][0], bh[nb][2]);
                    mma_bf16(acc[mi][2*nb+1], ah[mi], bh[nb][1], bh[nb][3]);
                }
            // phase 2: hi x lo
            #pragma unroll
            for (int mi = 0; mi < 2; mi++)
                #pragma unroll
                for (int nb = 0; nb < 2; nb++) {
                    mma_bf16(acc[mi][2*nb],   ah[mi], bl[nb][0], bl[nb][2]);
                    mma_bf16(acc[mi][2*nb+1], ah[mi], bl[nb][1], bl[nb][3]);
                }
            // phase 3: lo x hi
            #pragma unroll
            for (int mi = 0; mi < 2; mi++)
                #pragma unroll
                for (int nb = 0; nb < 2; nb++) {
                    mma_bf16(acc[mi][2*nb],   al[mi], bh[nb][0], bh[nb][2]);
                    mma_bf16(acc[mi][2*nb+1], al[mi], bh[nb][1], bh[nb][3]);
                }
        }
        __syncthreads();     // all warps done with buffer (c&1) before reuse
    }

    const int ql = lane >> 2;
    const int rl = (lane & 3) * 2;
    #pragma unroll
    for (int mi = 0; mi < 2; mi++) {
        const int m = bm + wm * 32 + mi * 16 + ql;
        #pragma unroll
        for (int nj = 0; nj < 4; nj++) {
            const int n = bn + wn * 32 + nj * 8 + rl;
            const float bz0 = bias[n], bz1 = bias[n + 1];
            if (cf) {
                float2 v;
                v.x = acc[mi][nj][0] + bz0; v.y = acc[mi][nj][1] + bz1;
                *(float2*)(cf + (size_t)m * N + n) = v;
                v.x = acc[mi][nj][2] + bz0; v.y = acc[mi][nj][3] + bz1;
                *(float2*)(cf + (size_t)(m + 8) * N + n) = v;
            } else {
                uint32_t h, l;
                split_pair((acc[mi][nj][0] + bz0) * scale,
                           (acc[mi][nj][1] + bz1) * scale, h, l);
                *(uint32_t*)(chi + (size_t)m * N + n) = h;
                *(uint32_t*)(clo + (size_t)m * N + n) = l;
                split_pair((acc[mi][nj][2] + bz0) * scale,
                           (acc[mi][nj][3] + bz1) * scale, h, l);
                *(uint32_t*)(chi + (size_t)(m + 8) * N + n) = h;
                *(uint32_t*)(clo + (size_t)(m + 8) * N + n) = l;
            }
        }
    }
}

// ===========================================================================
// Tensor-core flash attention, SPLIT-KEY (R12 proven): 512 thr/16 warps.
// Warp (wr, gj): wr = wid&7 owns q-rows [16wr,16wr+16); gj = wid>>3 owns
// key half [64gj, 64gj+64). Exact online softmax per group; flash merge.
// Band eb range per warp: [7+4gj-wr, 11+4gj-wr].
// QK loop: ks outer (same-acc dep distance 18, was 1); acc0/acc1 interleave.
// Per-accumulator addition order unchanged (bit-identical numerics).
// ===========================================================================
#define AKS 144
#define A_KHI 0
#define A_KLO 18432
#define A_VHI 36864
#define A_VLO 55296
#define A_EHI 73728
#define A_ELO 110592
#define A_S   147456
#define ATT_SMEM (A_S + 128 * 132 * 4)    // 215040 B

__global__ __launch_bounds__(512, 1)
void attn_tc_kernel(const bf16* __restrict__ qhi, const bf16* __restrict__ qlo,
                    const bf16* __restrict__ khi, const bf16* __restrict__ klo,
                    const bf16* __restrict__ vhi, const bf16* __restrict__ vlo,
                    const bf16* __restrict__ ehi, const bf16* __restrict__ elo,
                    bf16* __restrict__ chi, bf16* __restrict__ clo)
{
    extern __shared__ char sm[];
    const uint32_t sb = smem_u32(sm);
    float* sS = (float*)(sm + A_S);

    const int tid  = threadIdx.x;
    const int lane = tid & 31;
    const int wid  = tid >> 5;
    const int wr   = wid & 7;            // q-row group
    const int gj   = wid >> 3;           // key half
    const int g    = lane >> 2;
    const int rl   = lane & 3;
    const int i0   = blockIdx.x * 128;
    const int h    = blockIdx.y;
    const int b    = blockIdx.z;
    const size_t tokq = (size_t)(b * LL + i0);

    // ---- stage Q (hi/lo) into S region, grab A-frags ----
    {
        const int r = tid >> 2, ch = (tid & 3) * 16;
        const bf16* ph = qhi + (tokq + r) * DD + h * HDp + ch;
        const bf16* pl = qlo + (tokq + r) * DD + h * HDp + ch;
        const uint32_t dh = sb + A_S + (uint32_t)(r * AKS + ch * 2);
        #pragma unroll
        for (int g2 = 0; g2 < 2; g2++) {
            cp16(dh + g2 * 16,         ph + g2 * 8);
            cp16(dh + 18432 + g2 * 16, pl + g2 * 8);
        }
        CP_WAIT_ALL();
    }
    __syncthreads();
    uint32_t qh[4][4], ql4[4][4];
    {
        const uint32_t aq = sb + A_S + (uint32_t)((wr * 16 + (lane & 15)) * AKS + (lane >> 4) * 16);
        #pragma unroll
        for (int ks = 0; ks < 4; ks++) {
            ldsm_x4(aq + ks * 32, qh[ks]);
            ldsm_x4(aq + 18432 + ks * 32, ql4[ks]);
        }
    }

    float m0 = -1e30f, m1 = -1e30f, den0 = 0.f, den1 = 0.f;
    float o[8][4];
    #pragma unroll
    for (int i = 0; i < 8; i++)
        #pragma unroll
        for (int r = 0; r < 4; r++) o[i][r] = 0.f;

    const int r0 = wr * 16 + g, r1 = r0 + 8;
    const int jlLo = 64 * gj, jlHi = jlLo + 64;
    const int ebLo = 7 + 4 * gj - wr, ebHi = 11 + 4 * gj - wr;

    for (int jt = 0; jt < LL / 128; jt++) {
        const int j0 = jt * 128;
        __syncthreads();   // prior tile's smem reads complete (and Q frags on jt=0)

        // ---- async loads: K hi/lo, V hi/lo (row-major), E hi/lo band ----
        {
            const int r = tid >> 2, ch = (tid & 3) * 16;
            const size_t gofs = ((size_t)(b * LL + j0 + r)) * DD + h * HDp + ch;
            const uint32_t drow = (uint32_t)(r * AKS + ch * 2);
            #pragma unroll
            for (int g2 = 0; g2 < 2; g2++) {
                cp16(sb + A_KHI + drow + g2 * 16, khi + gofs + g2 * 8);
                cp16(sb + A_KLO + drow + g2 * 16, klo + gofs + g2 * 8);
                cp16(sb + A_VHI + drow + g2 * 16, vhi + gofs + g2 * 8);
                cp16(sb + A_VLO + drow + g2 * 16, vlo + gofs + g2 * 8);
            }
        }
        {
            const int rb0 = 895 + j0 - i0;
            #pragma unroll
            for (int p = 0; p < 4; p++) {
                const int idx = tid + p * 512;
                const int li = idx >> 3, gcol = (idx & 7) * 8;
                const int r = rb0 + li;
                const int rc = (r < 0) ? 0 : r;
                const bool ok = (r >= 0);
                const uint32_t doff = (uint32_t)(li * AKS + gcol * 2);
                cp16z(sb + A_EHI + doff, ehi + (size_t)rc * HDp + gcol, ok);
                cp16z(sb + A_ELO + doff, elo + (size_t)rc * HDp + gcol, ok);
            }
        }
        CP_WAIT_ALL();
        __syncthreads();

        // ---- band mma: R = Q . E^T on warp's eb range, scatter to own half ----
        {
            const uint32_t be = sb + A_EHI + (uint32_t)((lane & 15) * AKS + (lane >> 4) * 16);
            #pragma unroll
            for (int eb = 0; eb < 16; eb++) {
                if (eb < ebLo || eb > ebHi) continue;
                float ba[2][4] = {{0, 0, 0, 0}, {0, 0, 0, 0}};
                #pragma unroll
                for (int ks = 0; ks < 4; ks++) {
                    uint32_t eh[4], el[4];
                    ldsm_x4(be + eb * (16 * AKS) + ks * 32, eh);
                    ldsm_x4(be + (A_ELO - A_EHI) + eb * (16 * AKS) + ks * 32, el);
                    mma_bf16(ba[0], qh[ks],  eh[0], eh[2]);
                    mma_bf16(ba[1], qh[ks],  eh[1], eh[3]);
                    mma_bf16(ba[0], qh[ks],  el[0], el[2]);
                    mma_bf16(ba[1], qh[ks],  el[1], el[3]);
                    mma_bf16(ba[0], ql4[ks], eh[0], eh[2]);
                    mma_bf16(ba[1], ql4[ks], eh[1], eh[3]);
                }
                #pragma unroll
                for (int hf = 0; hf < 2; hf++) {
                    const int li = (eb * 2 + hf) * 8 + rl * 2;
                    int jl;
                    jl = li + r0 - 127;     if (jl >= jlLo && jl < jlHi) sS[r0 * 132 + jl] = ba[hf][0];
                    jl = li + 1 + r0 - 127; if (jl >= jlLo && jl < jlHi) sS[r0 * 132 + jl] = ba[hf][1];
                    jl = li + r1 - 127;     if (jl >= jlLo && jl < jlHi) sS[r1 * 132 + jl] = ba[hf][2];
                    jl = li + 1 + r1 - 127; if (jl >= jlLo && jl < jlHi) sS[r1 * 132 + jl] = ba[hf][3];
                }
            }
        }

        // ---- QK mma on own key half (ks outer: same-acc dep distance 18) ----
        float acc[8][4];
        #pragma unroll
        for (int i = 0; i < 8; i++)
            #pragma unroll
            for (int r = 0; r < 4; r++) acc[i][r] = 0.f;
        {
            const uint32_t bk = sb + A_KHI + (uint32_t)((lane & 15) * AKS + (lane >> 4) * 16);
            #pragma unroll
            for (int ks = 0; ks < 4; ks++) {
                #pragma unroll
                for (int a = 0; a < 4; a++) {
                    const int nb = 4 * gj + a;
                    uint32_t kh[4], kl[4];
                    ldsm_x4(bk + nb * (16 * AKS) + ks * 32, kh);
                    ldsm_x4(bk + (A_KLO - A_KHI) + nb * (16 * AKS) + ks * 32, kl);
                    mma_bf16(acc[2*a],   qh[ks],  kh[0], kh[2]);
                    mma_bf16(acc[2*a+1], qh[ks],  kh[1], kh[3]);
                    mma_bf16(acc[2*a],   qh[ks],  kl[0], kl[2]);
                    mma_bf16(acc[2*a+1], qh[ks],  kl[1], kl[3]);
                    mma_bf16(acc[2*a],   ql4[ks], kh[0], kh[2]);
                    mma_bf16(acc[2*a+1], ql4[ks], kh[1], kh[3]);
                }
            }
        }

        // ---- add band, online softmax over own half ----
        {
            const float* s0 = sS + r0 * 132 + jlLo;
            const float* s1 = sS + r1 * 132 + jlLo;
            #pragma unroll
            for (int nb8 = 0; nb8 < 8; nb8++) {
                const int c = nb8 * 8 + rl * 2;
                acc[nb8][0] += s0[c];     acc[nb8][1] += s0[c + 1];
                acc[nb8][2] += s1[c];     acc[nb8][3] += s1[c + 1];
            }
            float mx0 = -1e30f, mx1 = -1e30f;
            #pragma unroll
            for (int nb8 = 0; nb8 < 8; nb8++) {
                mx0 = fmaxf(mx0, fmaxf(acc[nb8][0], acc[nb8][1]));
                mx1 = fmaxf(mx1, fmaxf(acc[nb8][2], acc[nb8][3]));
            }
            mx0 = fmaxf(mx0, __shfl_xor_sync(0xffffffffu, mx0, 1));
            mx0 = fmaxf(mx0, __shfl_xor_sync(0xffffffffu, mx0, 2));
            mx1 = fmaxf(mx1, __shfl_xor_sync(0xffffffffu, mx1, 1));
            mx1 = fmaxf(mx1, __shfl_xor_sync(0xffffffffu, mx1, 2));
            const float nm0 = fmaxf(m0, mx0), nm1 = fmaxf(m1, mx1);
            const float cr0 = __expf(m0 - nm0), cr1 = __expf(m1 - nm1);
            float s0s = 0.f, s1s = 0.f;
            #pragma unroll
            for (int nb8 = 0; nb8 < 8; nb8++) {
                acc[nb8][0] = __expf(acc[nb8][0] - nm0); s0s += acc[nb8][0];
                acc[nb8][1] = __expf(acc[nb8][1] - nm0); s0s += acc[nb8][1];
                acc[nb8][2] = __expf(acc[nb8][2] - nm1); s1s += acc[nb8][2];
                acc[nb8][3] = __expf(acc[nb8][3] - nm1); s1s += acc[nb8][3];
            }
            s0s += __shfl_xor_sync(0xffffffffu, s0s, 1);
            s0s += __shfl_xor_sync(0xffffffffu, s0s, 2);
            s1s += __shfl_xor_sync(0xffffffffu, s1s, 1);
            s1s += __shfl_xor_sync(0xffffffffu, s1s, 2);
            den0 = den0 * cr0 + s0s; den1 = den1 * cr1 + s1s;
            m0 = nm0; m1 = nm1;
            #pragma unroll
            for (int nd = 0; nd < 8; nd++) {
                o[nd][0] *= cr0; o[nd][1] *= cr0;
                o[nd][2] *= cr1; o[nd][3] *= cr1;
            }
        }

        // ---- PV mma: O += P . V over own key half ----
        {
            const uint32_t bv = sb + A_VHI + (uint32_t)((lane & 15) * AKS + (lane >> 4) * 16);
            #pragma unroll
            for (int kbl = 0; kbl < 4; kbl++) {
                const int kbv = 4 * gj + kbl;
                uint32_t ph4[4], pl4[4];
                split_pair(acc[2*kbl][0],   acc[2*kbl][1],   ph4[0], pl4[0]);
                split_pair(acc[2*kbl][2],   acc[2*kbl][3],   ph4[1], pl4[1]);
                split_pair(acc[2*kbl+1][0], acc[2*kbl+1][1], ph4[2], pl4[2]);
                split_pair(acc[2*kbl+1][2], acc[2*kbl+1][3], ph4[3], pl4[3]);
                #pragma unroll
                for (int dn = 0; dn < 4; dn++) {
                    uint32_t vh[4], vl[4];
                    ldsm_x4t(bv + kbv * (16 * AKS) + dn * 32, vh);
                    ldsm_x4t(bv + (A_VLO - A_VHI) + kbv * (16 * AKS) + dn * 32, vl);
                    mma_bf16(o[2*dn],   ph4, vh[0], vh[1]);
                    mma_bf16(o[2*dn+1], ph4, vh[2], vh[3]);
                    mma_bf16(o[2*dn],   ph4, vl[0], vl[1]);
                    mma_bf16(o[2*dn+1], ph4, vl[2], vl[3]);
                    mma_bf16(o[2*dn],   pl4, vh[0], vh[1]);
                    mma_bf16(o[2*dn+1], pl4, vh[2], vh[3]);
                }
            }
        }
    }

    // ---- epilogue: merge the two key-half groups, normalize, store ----
    __syncthreads();               // all sS reads done; reuse sS for exchange
    {
        float* ex = sS;
        const int slot = (wr * 32 + lane) * 37;
        if (gj == 1) {
            ex[slot + 0] = m0; ex[slot + 1] = m1;
            ex[slot + 2] = den0; ex[slot + 3] = den1;
            #pragma unroll
            for (int nd = 0; nd < 8; nd++)
                #pragma unroll
                for (int r = 0; r < 4; r++)
                    ex[slot + 4 + nd * 4 + r] = o[nd][r];
        }
        __syncthreads();
        if (gj == 0) {
            const float mB0 = ex[slot + 0], mB1 = ex[slot + 1];
            const float dB0 = ex[slot + 2], dB1 = ex[slot + 3];
            const float M0 = fmaxf(m0, mB0), M1 = fmaxf(m1, mB1);
            const float sA0 = __expf(m0 - M0), sB0 = __expf(mB0 - M0);
            const float sA1 = __expf(m1 - M1), sB1 = __expf(mB1 - M1);
            const float inv0 = 1.f / (den0 * sA0 + dB0 * sB0);
            const float inv1 = 1.f / (den1 * sA1 + dB1 * sB1);
            const size_t t0 = tokq + r0, t1 = tokq + r1;
            #pragma unroll
            for (int nd = 0; nd < 8; nd++) {
                const int d = nd * 8 + rl * 2;
                const float* ob = ex + slot + 4 + nd * 4;
                uint32_t hw, lw;
                split_pair((o[nd][0] * sA0 + ob[0] * sB0) * inv0,
                           (o[nd][1] * sA0 + ob[1] * sB0) * inv0, hw, lw);
                *(uint32_t*)(chi + t0 * DD + h * HDp + d) = hw;
                *(uint32_t*)(clo + t0 * DD + h * HDp + d) = lw;
                split_pair((o[nd][2] * sA1 + ob[2] * sB1) * inv1,
                           (o[nd][3] * sA1 + ob[3] * sB1) * inv1, hw, lw);
                *(uint32_t*)(chi + t1 * DD + h * HDp + d) = hw;
                *(uint32_t*)(clo + t1 * DD + h * HDp + d) = lw;
            }
        }
    }
}

// ---------------------------------------------------------------------------
extern "C" void kernel_launch(void* const* d_in, const int* in_sizes, int n_in,
                              void* d_out, int out_size)
{
    const float* x  = (const float*)d_in[0];
    const float* Wq = (const float*)d_in[1];
    const float* bq = (const float*)d_in[2];
    const float* Wk = (const float*)d_in[3];
    const float* bk = (const float*)d_in[4];
    const float* Wv = (const float*)d_in[5];
    const float* bv = (const float*)d_in[6];
    const float* Wo = (const float*)d_in[7];
    const float* bo = (const float*)d_in[8];
    const float* E  = (const float*)d_in[9];
    float* out = (float*)d_out;

    bf16 *xhi, *xlo, *wqh, *wql, *wkh, *wkl, *wvh, *wvl, *woh, *wol;
    bf16 *qhi, *qlo, *khi, *klo, *vhi, *vlo, *ehi, *elo, *chi, *clo;
    cudaGetSymbolAddress((void**)&xhi, g_xhi); cudaGetSymbolAddress((void**)&xlo, g_xlo);
    cudaGetSymbolAddress((void**)&wqh, g_wqh); cudaGetSymbolAddress((void**)&wql, g_wql);
    cudaGetSymbolAddress((void**)&wkh, g_wkh); cudaGetSymbolAddress((void**)&wkl, g_wkl);
    cudaGetSymbolAddress((void**)&wvh, g_wvh); cudaGetSymbolAddress((void**)&wvl, g_wvl);
    cudaGetSymbolAddress((void**)&woh, g_woh); cudaGetSymbolAddress((void**)&wol, g_wol);
    cudaGetSymbolAddress((void**)&qhi, g_qhi); cudaGetSymbolAddress((void**)&qlo, g_qlo);
    cudaGetSymbolAddress((void**)&khi, g_khi); cudaGetSymbolAddress((void**)&klo, g_klo);
    cudaGetSymbolAddress((void**)&vhi, g_vhi); cudaGetSymbolAddress((void**)&vlo, g_vlo);
    cudaGetSymbolAddress((void**)&ehi, g_ehi); cudaGetSymbolAddress((void**)&elo, g_elo);
    cudaGetSymbolAddress((void**)&chi, g_chi); cudaGetSymbolAddress((void**)&clo, g_clo);

    cudaFuncSetAttribute(gemm_tc2_kernel,
                         cudaFuncAttributeMaxDynamicSharedMemorySize, GEMM_SMEM);
    cudaFuncSetAttribute(attn_tc_kernel,
                         cudaFuncAttributeMaxDynamicSharedMemorySize, ATT_SMEM);

    // 0) split all inputs into bf16 hi/lo (single launch)
    cvt_all_kernel<<<CVT_BLOCKS, 256>>>(x, Wq, Wk, Wv, Wo, E);

    // 1) fused QKV projections -> bf16 hi/lo q(scaled), k, v
    gemm_tc2_kernel<<<dim3(DD / 128, MM / 128, 3), 512, GEMM_SMEM>>>(
        xhi, xlo, wqh, wql, wkh, wkl, wvh, wvl, bq, bk, bv,
        qhi, qlo, khi, klo, vhi, vlo, nullptr, 0.125f, MM, DD, DD);

    // 2) tensor-core flash attention with rel-pos band (split-key, 16 warps)
    attn_tc_kernel<<<dim3(LL / 128, HH, Bb), 512, ATT_SMEM>>>(
        qhi, qlo, khi, klo, vhi, vlo, ehi, elo, chi, clo);

    // 3) output projection -> fp32 out
    gemm_tc2_kernel<<<dim3(DD / 128, MM / 128, 1), 512, GEMM_SMEM>>>(
        chi, clo, woh, wol, woh, wol, woh, wol, bo, bo, bo,
        nullptr, nullptr, nullptr, nullptr, nullptr, nullptr,
        out, 1.0f, MM, DD, DD);
}

// round 16
// speedup vs baseline: 1.5125x; 1.5125x over previous
#include <cuda_runtime.h>
#include <cuda_bf16.h>
#include <math.h>
#include <cstdint>

#define Bb   2
#define LL   1024
#define DD   1024
#define HH   16
#define HDp  64
#define MM   (Bb * LL)
#define NE   (2 * LL - 1)   // 2047

typedef __nv_bfloat16 bf16;

// Scratch (allocation-free rule: device globals)
__device__ bf16 g_xhi[MM * DD],  g_xlo[MM * DD];
__device__ bf16 g_wqh[DD * DD],  g_wql[DD * DD];
__device__ bf16 g_wkh[DD * DD],  g_wkl[DD * DD];
__device__ bf16 g_wvh[DD * DD],  g_wvl[DD * DD];
__device__ bf16 g_woh[DD * DD],  g_wol[DD * DD];
__device__ bf16 g_qhi[MM * DD],  g_qlo[MM * DD];
__device__ bf16 g_khi[MM * DD],  g_klo[MM * DD];
__device__ bf16 g_vhi[MM * DD],  g_vlo[MM * DD];
__device__ bf16 g_ehi[NE * HDp], g_elo[NE * HDp];
__device__ bf16 g_chi[MM * DD],  g_clo[MM * DD];

// ===========================================================================
// Helpers (sm_80+ ISA; proven on this toolchain)
// ===========================================================================
__device__ __forceinline__ uint32_t smem_u32(const void* p) {
    uint32_t a;
    asm("{ .reg .u64 t; cvta.to.shared.u64 t, %1; cvt.u32.u64 %0, t; }"
        : "=r"(a) : "l"(p));
    return a;
}
__device__ __forceinline__ void ldsm_x4(uint32_t addr, uint32_t r[4]) {
    asm volatile("ldmatrix.sync.aligned.m8n8.x4.shared.b16 {%0,%1,%2,%3}, [%4];"
                 : "=r"(r[0]), "=r"(r[1]), "=r"(r[2]), "=r"(r[3]) : "r"(addr));
}
__device__ __forceinline__ void ldsm_x4t(uint32_t addr, uint32_t r[4]) {
    asm volatile("ldmatrix.sync.aligned.m8n8.x4.trans.shared.b16 {%0,%1,%2,%3}, [%4];"
                 : "=r"(r[0]), "=r"(r[1]), "=r"(r[2]), "=r"(r[3]) : "r"(addr));
}
__device__ __forceinline__ void mma_bf16(float c[4], const uint32_t a[4],
                                         uint32_t b0, uint32_t b1) {
    asm volatile(
        "mma.sync.aligned.m16n8k16.row.col.f32.bf16.bf16.f32 "
        "{%0,%1,%2,%3}, {%4,%5,%6,%7}, {%8,%9}, {%0,%1,%2,%3};"
        : "+f"(c[0]), "+f"(c[1]), "+f"(c[2]), "+f"(c[3])
        : "r"(a[0]), "r"(a[1]), "r"(a[2]), "r"(a[3]), "r"(b0), "r"(b1));
}
__device__ __forceinline__ void cp16(uint32_t dst, const void* src) {
    asm volatile("cp.async.ca.shared.global [%0], [%1], 16;"
                 :: "r"(dst), "l"(src));
}
__device__ __forceinline__ void cp16z(uint32_t dst, const void* src, bool pred) {
    int sz = pred ? 16 : 0;
    asm volatile("cp.async.ca.shared.global [%0], [%1], 16, %2;"
                 :: "r"(dst), "l"(src), "r"(sz));
}
#define CP_COMMIT() asm volatile("cp.async.commit_group;" ::: "memory")
#define CP_WAIT0()  asm volatile("cp.async.wait_group 0;" ::: "memory")
#define CP_WAIT1()  asm volatile("cp.async.wait_group 1;" ::: "memory")
#define CP_WAIT_ALL() do { CP_COMMIT(); CP_WAIT0(); } while (0)

__device__ __forceinline__ uint32_t pack2(bf16 a, bf16 b) {
    return (uint32_t)__bfloat16_as_ushort(a) | ((uint32_t)__bfloat16_as_ushort(b) << 16);
}
__device__ __forceinline__ void split_pair(float a, float b, uint32_t& hi, uint32_t& lo) {
    bf16 ha = __float2bfloat16(a), hb = __float2bfloat16(b);
    hi = pack2(ha, hb);
    lo = pack2(__float2bfloat16(a - __bfloat162float(ha)),
               __float2bfloat16(b - __bfloat162float(hb)));
}

// ===========================================================================
// fp32 -> bf16 hi/lo split, all tensors in ONE launch (segment dispatch)
// ===========================================================================
#define SEG0 (MM * DD)
#define SEG1 (SEG0 + DD * DD)
#define SEG2 (SEG1 + DD * DD)
#define SEG3 (SEG2 + DD * DD)
#define SEG4 (SEG3 + DD * DD)
#define SEG5 (SEG4 + NE * HDp)
#define CVT_BLOCKS ((SEG5 / 4 + 255) / 256)

__global__ void cvt_all_kernel(const float* __restrict__ x,  const float* __restrict__ Wq,
                               const float* __restrict__ Wk, const float* __restrict__ Wv,
                               const float* __restrict__ Wo, const float* __restrict__ E)
{
    int i = (blockIdx.x * 256 + threadIdx.x) * 4;
    if (i >= SEG5) return;
    const float* s; bf16 *hi, *lo; int off;
    if      (i < SEG0) { s = x;  hi = g_xhi; lo = g_xlo; off = i; }
    else if (i < SEG1) { s = Wq; hi = g_wqh; lo = g_wql; off = i - SEG0; }
    else if (i < SEG2) { s = Wk; hi = g_wkh; lo = g_wkl; off = i - SEG1; }
    else if (i < SEG3) { s = Wv; hi = g_wvh; lo = g_wvl; off = i - SEG2; }
    else if (i < SEG4) { s = Wo; hi = g_woh; lo = g_wol; off = i - SEG3; }
    else               { s = E;  hi = g_ehi; lo = g_elo; off = i - SEG4; }
    float4 v = *(const float4*)(s + off);
    uint32_t h0, l0, h1, l1;
    split_pair(v.x, v.y, h0, l0);
    split_pair(v.z, v.w, h1, l1);
    *(uint2*)(hi + off) = make_uint2(h0, h1);
    *(uint2*)(lo + off) = make_uint2(l0, l1);
}

// ===========================================================================
// Tensor-core GEMM: C = A(MxK) @ W(NxK)^T + bias, pre-split bf16 inputs.
// 128x128 CTA tile, 512 threads / 16 warps (4m x 4n), warp tile 32x32
// (squarer -> fewer ldsm per mma). K chunks of 64, 2-stage cp.async pipeline.
// ===========================================================================
#define GSA     144
#define GTILE_B (128 * GSA)
#define OFF_AHI 0
#define OFF_ALO GTILE_B
#define OFF_BHI (2 * GTILE_B)
#define OFF_BLO (3 * GTILE_B)
#define GBUF_B  (4 * GTILE_B)            // 73728 per stage
#define GEMM_SMEM (2 * GBUF_B)           // 147456

__global__ __launch_bounds__(512, 1)
void gemm_tc2_kernel(const bf16* __restrict__ ahi, const bf16* __restrict__ alo,
                     const bf16* __restrict__ w0h, const bf16* __restrict__ w0l,
                     const bf16* __restrict__ w1h, const bf16* __restrict__ w1l,
                     const bf16* __restrict__ w2h, const bf16* __restrict__ w2l,
                     const float* __restrict__ b0, const float* __restrict__ b1,
                     const float* __restrict__ b2,
                     bf16* c0h, bf16* c0l, bf16* c1h, bf16* c1l,
                     bf16* c2h, bf16* c2l,
                     float* cf, float scale0, int M, int N, int K)
{
    const int z = blockIdx.z;
    const bf16* wh   = (z == 0) ? w0h : (z == 1 ? w1h : w2h);
    const bf16* wl   = (z == 0) ? w0l : (z == 1 ? w1l : w2l);
    const float* bias = (z == 0) ? b0 : (z == 1 ? b1 : b2);
    bf16* chi = (z == 0) ? c0h : (z == 1 ? c1h : c2h);
    bf16* clo = (z == 0) ? c0l : (z == 1 ? c1l : c2l);
    const float scale = (z == 0) ? scale0 : 1.0f;

    extern __shared__ char sm[];
    const uint32_t sbase = smem_u32(sm);

    const int tid  = threadIdx.x;
    const int lane = tid & 31;
    const int wid  = tid >> 5;
    const int wm   = wid & 3;            // 0..3  (32 rows each)
    const int wn   = wid >> 2;           // 0..3  (32 cols each)
    const int bm   = blockIdx.y * 128;
    const int bn   = blockIdx.x * 128;

    float acc[2][4][4];
    #pragma unroll
    for (int i = 0; i < 2; i++)
        #pragma unroll
        for (int j = 0; j < 4; j++)
            #pragma unroll
            for (int r = 0; r < 4; r++) acc[i][j][r] = 0.f;

    // fill mapping: 512 threads, row = tid>>2 (128 rows), quarter = (tid&3)*16 bf16
    const int frow = tid >> 2;
    const int fcol = (tid & 3) * 16;
    const bf16* pah = ahi + (size_t)(bm + frow) * K + fcol;
    const bf16* pal = alo + (size_t)(bm + frow) * K + fcol;
    const bf16* pwh = wh  + (size_t)(bn + frow) * K + fcol;
    const bf16* pwl = wl  + (size_t)(bn + frow) * K + fcol;
    const uint32_t dstrow = (uint32_t)(frow * GSA + fcol * 2);

    const int lr   = lane & 15;
    const int lc16 = (lane >> 4) * 16;
    const uint32_t a_rel = (uint32_t)((wm * 32 + lr) * GSA + lc16);
    const uint32_t b_rel = (uint32_t)((wn * 32 + lr) * GSA + lc16);

    // prologue: issue chunk 0 into buffer 0
    {
        const uint32_t d = sbase + dstrow;
        #pragma unroll
        for (int g = 0; g < 2; g++) {
            cp16(d + OFF_AHI + g * 16, pah + g * 8);
            cp16(d + OFF_ALO + g * 16, pal + g * 8);
            cp16(d + OFF_BHI + g * 16, pwh + g * 8);
            cp16(d + OFF_BLO + g * 16, pwl + g * 8);
        }
        CP_COMMIT();
    }

    const int NCH = K / 64;
    for (int c = 0; c < NCH; c++) {
        if (c + 1 < NCH) {
            const int kb = (c + 1) * 64;
            const uint32_t d = sbase + ((c + 1) & 1) * GBUF_B + dstrow;
            #pragma unroll
            for (int g = 0; g < 2; g++) {
                cp16(d + OFF_AHI + g * 16, pah + kb + g * 8);
                cp16(d + OFF_ALO + g * 16, pal + kb + g * 8);
                cp16(d + OFF_BHI + g * 16, pwh + kb + g * 8);
                cp16(d + OFF_BLO + g * 16, pwl + kb + g * 8);
            }
            CP_COMMIT();
            CP_WAIT1();      // chunk c complete (c+1 still in flight)
        } else {
            CP_WAIT0();
        }
        __syncthreads();     // chunk c visible to all warps

        const uint32_t a_lane = sbase + (c & 1) * GBUF_B + a_rel;
        const uint32_t b_lane = sbase + (c & 1) * GBUF_B + b_rel;
        #pragma unroll
        for (int ks = 0; ks < 4; ks++) {
            const uint32_t cb = (uint32_t)(ks * 32);
            uint32_t ah[2][4], al[2][4];
            #pragma unroll
            for (int mi = 0; mi < 2; mi++) {
                ldsm_x4(a_lane + OFF_AHI + mi * (16 * GSA) + cb, ah[mi]);
                ldsm_x4(a_lane + OFF_ALO + mi * (16 * GSA) + cb, al[mi]);
            }
            uint32_t bh[2][4], bl[2][4];
            #pragma unroll
            for (int nb = 0; nb < 2; nb++) {
                ldsm_x4(b_lane + OFF_BHI + nb * (16 * GSA) + cb, bh[nb]);
                ldsm_x4(b_lane + OFF_BLO + nb * (16 * GSA) + cb, bl[nb]);
            }
            #pragma unroll
            for (int mi = 0; mi < 2; mi++)
                #pragma unroll
                for (int nb = 0; nb < 2; nb++) {
                    mma_bf16(acc[mi][2*nb],   ah[mi], bh[nb][0], bh[nb][2]);
                    mma_bf16(acc[mi][2*nb],   ah[mi], bl[nb][0], bl[nb][2]);
                    mma_bf16(acc[mi][2*nb],   al[mi], bh[nb][0], bh[nb][2]);
                    mma_bf16(acc[mi][2*nb+1], ah[mi], bh[nb][1], bh[nb][3]);
                    mma_bf16(acc[mi][2*nb+1], ah[mi], bl[nb][1], bl[nb][3]);
                    mma_bf16(acc[mi][2*nb+1], al[mi], bh[nb][1], bh[nb][3]);
                }
        }
        __syncthreads();     // all warps done with buffer (c&1) before reuse
    }

    const int ql = lane >> 2;
    const int rl = (lane & 3) * 2;
    #pragma unroll
    for (int mi = 0; mi < 2; mi++) {
        const int m = bm + wm * 32 + mi * 16 + ql;
        #pragma unroll
        for (int nj = 0; nj < 4; nj++) {
            const int n = bn + wn * 32 + nj * 8 + rl;
            const float bz0 = bias[n], bz1 = bias[n + 1];
            if (cf) {
                float2 v;
                v.x = acc[mi][nj][0] + bz0; v.y = acc[mi][nj][1] + bz1;
                *(float2*)(cf + (size_t)m * N + n) = v;
                v.x = acc[mi][nj][2] + bz0; v.y = acc[mi][nj][3] + bz1;
                *(float2*)(cf + (size_t)(m + 8) * N + n) = v;
            } else {
                uint32_t h, l;
                split_pair((acc[mi][nj][0] + bz0) * scale,
                           (acc[mi][nj][1] + bz1) * scale, h, l);
                *(uint32_t*)(chi + (size_t)m * N + n) = h;
                *(uint32_t*)(clo + (size_t)m * N + n) = l;
                split_pair((acc[mi][nj][2] + bz0) * scale,
                           (acc[mi][nj][3] + bz1) * scale, h, l);
                *(uint32_t*)(chi + (size_t)(m + 8) * N + n) = h;
                *(uint32_t*)(clo + (size_t)(m + 8) * N + n) = l;
            }
        }
    }
}

// ===========================================================================
// Tensor-core flash attention, SPLIT-KEY version (R12 proven): 512 thr/16 w.
// Warp (wr, gj): wr = wid&7 owns q-rows [16wr,16wr+16); gj = wid>>3 owns
// key half [64gj, 64gj+64). Exact online softmax per group; flash merge.
// Band eb range per warp: [7+4gj-wr, 11+4gj-wr].
// ===========================================================================
#define AKS 144
#define A_KHI 0
#define A_KLO 18432
#define A_VHI 36864
#define A_VLO 55296
#define A_EHI 73728
#define A_ELO 110592
#define A_S   147456
#define ATT_SMEM (A_S + 128 * 132 * 4)    // 215040 B

__global__ __launch_bounds__(512, 1)
void attn_tc_kernel(const bf16* __restrict__ qhi, const bf16* __restrict__ qlo,
                    const bf16* __restrict__ khi, const bf16* __restrict__ klo,
                    const bf16* __restrict__ vhi, const bf16* __restrict__ vlo,
                    const bf16* __restrict__ ehi, const bf16* __restrict__ elo,
                    bf16* __restrict__ chi, bf16* __restrict__ clo)
{
    extern __shared__ char sm[];
    const uint32_t sb = smem_u32(sm);
    float* sS = (float*)(sm + A_S);

    const int tid  = threadIdx.x;
    const int lane = tid & 31;
    const int wid  = tid >> 5;
    const int wr   = wid & 7;            // q-row group
    const int gj   = wid >> 3;           // key half
    const int g    = lane >> 2;
    const int rl   = lane & 3;
    const int i0   = blockIdx.x * 128;
    const int h    = blockIdx.y;
    const int b    = blockIdx.z;
    const size_t tokq = (size_t)(b * LL + i0);

    // ---- stage Q (hi/lo) into S region, grab A-frags ----
    {
        const int r = tid >> 2, ch = (tid & 3) * 16;
        const bf16* ph = qhi + (tokq + r) * DD + h * HDp + ch;
        const bf16* pl = qlo + (tokq + r) * DD + h * HDp + ch;
        const uint32_t dh = sb + A_S + (uint32_t)(r * AKS + ch * 2);
        #pragma unroll
        for (int g2 = 0; g2 < 2; g2++) {
            cp16(dh + g2 * 16,         ph + g2 * 8);
            cp16(dh + 18432 + g2 * 16, pl + g2 * 8);
        }
        CP_WAIT_ALL();
    }
    __syncthreads();
    uint32_t qh[4][4], ql4[4][4];
    {
        const uint32_t aq = sb + A_S + (uint32_t)((wr * 16 + (lane & 15)) * AKS + (lane >> 4) * 16);
        #pragma unroll
        for (int ks = 0; ks < 4; ks++) {
            ldsm_x4(aq + ks * 32, qh[ks]);
            ldsm_x4(aq + 18432 + ks * 32, ql4[ks]);
        }
    }

    float m0 = -1e30f, m1 = -1e30f, den0 = 0.f, den1 = 0.f;
    float o[8][4];
    #pragma unroll
    for (int i = 0; i < 8; i++)
        #pragma unroll
        for (int r = 0; r < 4; r++) o[i][r] = 0.f;

    const int r0 = wr * 16 + g, r1 = r0 + 8;
    const int jlLo = 64 * gj, jlHi = jlLo + 64;
    const int ebLo = 7 + 4 * gj - wr, ebHi = 11 + 4 * gj - wr;

    for (int jt = 0; jt < LL / 128; jt++) {
        const int j0 = jt * 128;
        __syncthreads();   // prior tile's smem reads complete (and Q frags on jt=0)

        // ---- async loads: K hi/lo, V hi/lo (row-major), E hi/lo band ----
        {
            const int r = tid >> 2, ch = (tid & 3) * 16;
            const size_t gofs = ((size_t)(b * LL + j0 + r)) * DD + h * HDp + ch;
            const uint32_t drow = (uint32_t)(r * AKS + ch * 2);
            #pragma unroll
            for (int g2 = 0; g2 < 2; g2++) {
                cp16(sb + A_KHI + drow + g2 * 16, khi + gofs + g2 * 8);
                cp16(sb + A_KLO + drow + g2 * 16, klo + gofs + g2 * 8);
                cp16(sb + A_VHI + drow + g2 * 16, vhi + gofs + g2 * 8);
                cp16(sb + A_VLO + drow + g2 * 16, vlo + gofs + g2 * 8);
            }
        }
        {
            const int rb0 = 895 + j0 - i0;
            #pragma unroll
            for (int p = 0; p < 4; p++) {
                const int idx = tid + p * 512;
                const int li = idx >> 3, gcol = (idx & 7) * 8;
                const int r = rb0 + li;
                const int rc = (r < 0) ? 0 : r;
                const bool ok = (r >= 0);
                const uint32_t doff = (uint32_t)(li * AKS + gcol * 2);
                cp16z(sb + A_EHI + doff, ehi + (size_t)rc * HDp + gcol, ok);
                cp16z(sb + A_ELO + doff, elo + (size_t)rc * HDp + gcol, ok);
            }
        }
        CP_WAIT_ALL();
        __syncthreads();

        // ---- band mma: R = Q . E^T on warp's eb range, scatter to own half ----
        {
            const uint32_t be = sb + A_EHI + (uint32_t)((lane & 15) * AKS + (lane >> 4) * 16);
            #pragma unroll
            for (int eb = 0; eb < 16; eb++) {
                if (eb < ebLo || eb > ebHi) continue;
                float ba[2][4] = {{0, 0, 0, 0}, {0, 0, 0, 0}};
                #pragma unroll
                for (int ks = 0; ks < 4; ks++) {
                    uint32_t eh[4], el[4];
                    ldsm_x4(be + eb * (16 * AKS) + ks * 32, eh);
                    ldsm_x4(be + (A_ELO - A_EHI) + eb * (16 * AKS) + ks * 32, el);
                    mma_bf16(ba[0], qh[ks],  eh[0], eh[2]);
                    mma_bf16(ba[0], qh[ks],  el[0], el[2]);
                    mma_bf16(ba[0], ql4[ks], eh[0], eh[2]);
                    mma_bf16(ba[1], qh[ks],  eh[1], eh[3]);
                    mma_bf16(ba[1], qh[ks],  el[1], el[3]);
                    mma_bf16(ba[1], ql4[ks], eh[1], eh[3]);
                }
                #pragma unroll
                for (int hf = 0; hf < 2; hf++) {
                    const int li = (eb * 2 + hf) * 8 + rl * 2;
                    int jl;
                    jl = li + r0 - 127;     if (jl >= jlLo && jl < jlHi) sS[r0 * 132 + jl] = ba[hf][0];
                    jl = li + 1 + r0 - 127; if (jl >= jlLo && jl < jlHi) sS[r0 * 132 + jl] = ba[hf][1];
                    jl = li + r1 - 127;     if (jl >= jlLo && jl < jlHi) sS[r1 * 132 + jl] = ba[hf][2];
                    jl = li + 1 + r1 - 127; if (jl >= jlLo && jl < jlHi) sS[r1 * 132 + jl] = ba[hf][3];
                }
            }
        }

        // ---- QK mma on own key half ----
        float acc[8][4];
        #pragma unroll
        for (int i = 0; i < 8; i++)
            #pragma unroll
            for (int r = 0; r < 4; r++) acc[i][r] = 0.f;
        {
            const uint32_t bk = sb + A_KHI + (uint32_t)((lane & 15) * AKS + (lane >> 4) * 16);
            #pragma unroll
            for (int a = 0; a < 4; a++) {
                const int nb = 4 * gj + a;
                #pragma unroll
                for (int ks = 0; ks < 4; ks++) {
                    uint32_t kh[4], kl[4];
                    ldsm_x4(bk + nb * (16 * AKS) + ks * 32, kh);
                    ldsm_x4(bk + (A_KLO - A_KHI) + nb * (16 * AKS) + ks * 32, kl);
                    mma_bf16(acc[2*a],   qh[ks],  kh[0], kh[2]);
                    mma_bf16(acc[2*a],   qh[ks],  kl[0], kl[2]);
                    mma_bf16(acc[2*a],   ql4[ks], kh[0], kh[2]);
                    mma_bf16(acc[2*a+1], qh[ks],  kh[1], kh[3]);
                    mma_bf16(acc[2*a+1], qh[ks],  kl[1], kl[3]);
                    mma_bf16(acc[2*a+1], ql4[ks], kh[1], kh[3]);
                }
            }
        }

        // ---- add band, online softmax over own half ----
        {
            const float* s0 = sS + r0 * 132 + jlLo;
            const float* s1 = sS + r1 * 132 + jlLo;
            #pragma unroll
            for (int nb8 = 0; nb8 < 8; nb8++) {
                const int c = nb8 * 8 + rl * 2;
                acc[nb8][0] += s0[c];     acc[nb8][1] += s0[c + 1];
                acc[nb8][2] += s1[c];     acc[nb8][3] += s1[c + 1];
            }
            float mx0 = -1e30f, mx1 = -1e30f;
            #pragma unroll
            for (int nb8 = 0; nb8 < 8; nb8++) {
                mx0 = fmaxf(mx0, fmaxf(acc[nb8][0], acc[nb8][1]));
                mx1 = fmaxf(mx1, fmaxf(acc[nb8][2], acc[nb8][3]));
            }
            mx0 = fmaxf(mx0, __shfl_xor_sync(0xffffffffu, mx0, 1));
            mx0 = fmaxf(mx0, __shfl_xor_sync(0xffffffffu, mx0, 2));
            mx1 = fmaxf(mx1, __shfl_xor_sync(0xffffffffu, mx1, 1));
            mx1 = fmaxf(mx1, __shfl_xor_sync(0xffffffffu, mx1, 2));
            const float nm0 = fmaxf(m0, mx0), nm1 = fmaxf(m1, mx1);
            const float cr0 = __expf(m0 - nm0), cr1 = __expf(m1 - nm1);
            float s0s = 0.f, s1s = 0.f;
            #pragma unroll
            for (int nb8 = 0; nb8 < 8; nb8++) {
                acc[nb8][0] = __expf(acc[nb8][0] - nm0); s0s += acc[nb8][0];
                acc[nb8][1] = __expf(acc[nb8][1] - nm0); s0s += acc[nb8][1];
                acc[nb8][2] = __expf(acc[nb8][2] - nm1); s1s += acc[nb8][2];
                acc[nb8][3] = __expf(acc[nb8][3] - nm1); s1s += acc[nb8][3];
            }
            s0s += __shfl_xor_sync(0xffffffffu, s0s, 1);
            s0s += __shfl_xor_sync(0xffffffffu, s0s, 2);
            s1s += __shfl_xor_sync(0xffffffffu, s1s, 1);
            s1s += __shfl_xor_sync(0xffffffffu, s1s, 2);
            den0 = den0 * cr0 + s0s; den1 = den1 * cr1 + s1s;
            m0 = nm0; m1 = nm1;
            #pragma unroll
            for (int nd = 0; nd < 8; nd++) {
                o[nd][0] *= cr0; o[nd][1] *= cr0;
                o[nd][2] *= cr1; o[nd][3] *= cr1;
            }
        }

        // ---- PV mma: O += P . V over own key half ----
        {
            const uint32_t bv = sb + A_VHI + (uint32_t)((lane & 15) * AKS + (lane >> 4) * 16);
            #pragma unroll
            for (int kbl = 0; kbl < 4; kbl++) {
                const int kbv = 4 * gj + kbl;
                uint32_t ph4[4], pl4[4];
                split_pair(acc[2*kbl][0],   acc[2*kbl][1],   ph4[0], pl4[0]);
                split_pair(acc[2*kbl][2],   acc[2*kbl][3],   ph4[1], pl4[1]);
                split_pair(acc[2*kbl+1][0], acc[2*kbl+1][1], ph4[2], pl4[2]);
                split_pair(acc[2*kbl+1][2], acc[2*kbl+1][3], ph4[3], pl4[3]);
                #pragma unroll
                for (int dn = 0; dn < 4; dn++) {
                    uint32_t vh[4], vl[4];
                    ldsm_x4t(bv + kbv * (16 * AKS) + dn * 32, vh);
                    ldsm_x4t(bv + (A_VLO - A_VHI) + kbv * (16 * AKS) + dn * 32, vl);
                    mma_bf16(o[2*dn],   ph4, vh[0], vh[1]);
                    mma_bf16(o[2*dn],   ph4, vl[0], vl[1]);
                    mma_bf16(o[2*dn],   pl4, vh[0], vh[1]);
                    mma_bf16(o[2*dn+1], ph4, vh[2], vh[3]);
                    mma_bf16(o[2*dn+1], ph4, vl[2], vl[3]);
                    mma_bf16(o[2*dn+1], pl4, vh[2], vh[3]);
                }
            }
        }
    }

    // ---- epilogue: merge the two key-half groups, normalize, store ----
    __syncthreads();               // all sS reads done; reuse sS for exchange
    {
        float* ex = sS;
        const int slot = (wr * 32 + lane) * 37;
        if (gj == 1) {
            ex[slot + 0] = m0; ex[slot + 1] = m1;
            ex[slot + 2] = den0; ex[slot + 3] = den1;
            #pragma unroll
            for (int nd = 0; nd < 8; nd++)
                #pragma unroll
                for (int r = 0; r < 4; r++)
                    ex[slot + 4 + nd * 4 + r] = o[nd][r];
        }
        __syncthreads();
        if (gj == 0) {
            const float mB0 = ex[slot + 0], mB1 = ex[slot + 1];
            const float dB0 = ex[slot + 2], dB1 = ex[slot + 3];
            const float M0 = fmaxf(m0, mB0), M1 = fmaxf(m1, mB1);
            const float sA0 = __expf(m0 - M0), sB0 = __expf(mB0 - M0);
            const float sA1 = __expf(m1 - M1), sB1 = __expf(mB1 - M1);
            const float inv0 = 1.f / (den0 * sA0 + dB0 * sB0);
            const float inv1 = 1.f / (den1 * sA1 + dB1 * sB1);
            const size_t t0 = tokq + r0, t1 = tokq + r1;
            #pragma unroll
            for (int nd = 0; nd < 8; nd++) {
                const int d = nd * 8 + rl * 2;
                const float* ob = ex + slot + 4 + nd * 4;
                uint32_t hw, lw;
                split_pair((o[nd][0] * sA0 + ob[0] * sB0) * inv0,
                           (o[nd][1] * sA0 + ob[1] * sB0) * inv0, hw, lw);
                *(uint32_t*)(chi + t0 * DD + h * HDp + d) = hw;
                *(uint32_t*)(clo + t0 * DD + h * HDp + d) = lw;
                split_pair((o[nd][2] * sA1 + ob[2] * sB1) * inv1,
                           (o[nd][3] * sA1 + ob[3] * sB1) * inv1, hw, lw);
                *(uint32_t*)(chi + t1 * DD + h * HDp + d) = hw;
                *(uint32_t*)(clo + t1 * DD + h * HDp + d) = lw;
            }
        }
    }
}

// ---------------------------------------------------------------------------
extern "C" void kernel_launch(void* const* d_in, const int* in_sizes, int n_in,
                              void* d_out, int out_size)
{
    const float* x  = (const float*)d_in[0];
    const float* Wq = (const float*)d_in[1];
    const float* bq = (const float*)d_in[2];
    const float* Wk = (const float*)d_in[3];
    const float* bk = (const float*)d_in[4];
    const float* Wv = (const float*)d_in[5];
    const float* bv = (const float*)d_in[6];
    const float* Wo = (const float*)d_in[7];
    const float* bo = (const float*)d_in[8];
    const float* E  = (const float*)d_in[9];
    float* out = (float*)d_out;

    bf16 *xhi, *xlo, *wqh, *wql, *wkh, *wkl, *wvh, *wvl, *woh, *wol;
    bf16 *qhi, *qlo, *khi, *klo, *vhi, *vlo, *ehi, *elo, *chi, *clo;
    cudaGetSymbolAddress((void**)&xhi, g_xhi); cudaGetSymbolAddress((void**)&xlo, g_xlo);
    cudaGetSymbolAddress((void**)&wqh, g_wqh); cudaGetSymbolAddress((void**)&wql, g_wql);
    cudaGetSymbolAddress((void**)&wkh, g_wkh); cudaGetSymbolAddress((void**)&wkl, g_wkl);
    cudaGetSymbolAddress((void**)&wvh, g_wvh); cudaGetSymbolAddress((void**)&wvl, g_wvl);
    cudaGetSymbolAddress((void**)&woh, g_woh); cudaGetSymbolAddress((void**)&wol, g_wol);
    cudaGetSymbolAddress((void**)&qhi, g_qhi); cudaGetSymbolAddress((void**)&qlo, g_qlo);
    cudaGetSymbolAddress((void**)&khi, g_khi); cudaGetSymbolAddress((void**)&klo, g_klo);
    cudaGetSymbolAddress((void**)&vhi, g_vhi); cudaGetSymbolAddress((void**)&vlo, g_vlo);
    cudaGetSymbolAddress((void**)&ehi, g_ehi); cudaGetSymbolAddress((void**)&elo, g_elo);
    cudaGetSymbolAddress((void**)&chi, g_chi); cudaGetSymbolAddress((void**)&clo, g_clo);

    cudaFuncSetAttribute(gemm_tc2_kernel,
                         cudaFuncAttributeMaxDynamicSharedMemorySize, GEMM_SMEM);
    cudaFuncSetAttribute(attn_tc_kernel,
                         cudaFuncAttributeMaxDynamicSharedMemorySize, ATT_SMEM);

    // 0) split all inputs into bf16 hi/lo (single launch)
    cvt_all_kernel<<<CVT_BLOCKS, 256>>>(x, Wq, Wk, Wv, Wo, E);

    // 1) fused QKV projections -> bf16 hi/lo q(scaled), k, v
    gemm_tc2_kernel<<<dim3(DD / 128, MM / 128, 3), 512, GEMM_SMEM>>>(
        xhi, xlo, wqh, wql, wkh, wkl, wvh, wvl, bq, bk, bv,
        qhi, qlo, khi, klo, vhi, vlo, nullptr, 0.125f, MM, DD, DD);

    // 2) tensor-core flash attention with rel-pos band (split-key, 16 warps)
    attn_tc_kernel<<<dim3(LL / 128, HH, Bb), 512, ATT_SMEM>>>(
        qhi, qlo, khi, klo, vhi, vlo, ehi, elo, chi, clo);

    // 3) output projection -> fp32 out
    gemm_tc2_kernel<<<dim3(DD / 128, MM / 128, 1), 512, GEMM_SMEM>>>(
        chi, clo, woh, wol, woh, wol, woh, wol, bo, bo, bo,
        nullptr, nullptr, nullptr, nullptr, nullptr, nullptr,
        out, 1.0f, MM, DD, DD);
}

// round 17
// speedup vs baseline: 1.5394x; 1.0178x over previous
#include <cuda_runtime.h>
#include <cuda_bf16.h>
#include <math.h>
#include <cstdint>

#define Bb   2
#define LL   1024
#define DD   1024
#define HH   16
#define HDp  64
#define MM   (Bb * LL)
#define NE   (2 * LL - 1)   // 2047

typedef __nv_bfloat16 bf16;

// Scratch (allocation-free rule: device globals)
__device__ bf16 g_xhi[MM * DD],  g_xlo[MM * DD];
__device__ bf16 g_wqh[DD * DD],  g_wql[DD * DD];
__device__ bf16 g_wkh[DD * DD],  g_wkl[DD * DD];
__device__ bf16 g_wvh[DD * DD],  g_wvl[DD * DD];
__device__ bf16 g_woh[DD * DD],  g_wol[DD * DD];
__device__ bf16 g_qhi[MM * DD],  g_qlo[MM * DD];
__device__ bf16 g_khi[MM * DD],  g_klo[MM * DD];
__device__ bf16 g_vhi[MM * DD],  g_vlo[MM * DD];
__device__ bf16 g_ehi[NE * HDp], g_elo[NE * HDp];
__device__ bf16 g_chi[MM * DD],  g_clo[MM * DD];

// ===========================================================================
// Helpers (sm_80+ ISA; proven on this toolchain)
// ===========================================================================
__device__ __forceinline__ uint32_t smem_u32(const void* p) {
    uint32_t a;
    asm("{ .reg .u64 t; cvta.to.shared.u64 t, %1; cvt.u32.u64 %0, t; }"
        : "=r"(a) : "l"(p));
    return a;
}
__device__ __forceinline__ void ldsm_x4(uint32_t addr, uint32_t r[4]) {
    asm volatile("ldmatrix.sync.aligned.m8n8.x4.shared.b16 {%0,%1,%2,%3}, [%4];"
                 : "=r"(r[0]), "=r"(r[1]), "=r"(r[2]), "=r"(r[3]) : "r"(addr));
}
__device__ __forceinline__ void ldsm_x4t(uint32_t addr, uint32_t r[4]) {
    asm volatile("ldmatrix.sync.aligned.m8n8.x4.trans.shared.b16 {%0,%1,%2,%3}, [%4];"
                 : "=r"(r[0]), "=r"(r[1]), "=r"(r[2]), "=r"(r[3]) : "r"(addr));
}
__device__ __forceinline__ void mma_bf16(float c[4], const uint32_t a[4],
                                         uint32_t b0, uint32_t b1) {
    asm volatile(
        "mma.sync.aligned.m16n8k16.row.col.f32.bf16.bf16.f32 "
        "{%0,%1,%2,%3}, {%4,%5,%6,%7}, {%8,%9}, {%0,%1,%2,%3};"
        : "+f"(c[0]), "+f"(c[1]), "+f"(c[2]), "+f"(c[3])
        : "r"(a[0]), "r"(a[1]), "r"(a[2]), "r"(a[3]), "r"(b0), "r"(b1));
}
__device__ __forceinline__ void cp16(uint32_t dst, const void* src) {
    asm volatile("cp.async.ca.shared.global [%0], [%1], 16;"
                 :: "r"(dst), "l"(src));
}
__device__ __forceinline__ void cp16z(uint32_t dst, const void* src, bool pred) {
    int sz = pred ? 16 : 0;
    asm volatile("cp.async.ca.shared.global [%0], [%1], 16, %2;"
                 :: "r"(dst), "l"(src), "r"(sz));
}
#define CP_COMMIT() asm volatile("cp.async.commit_group;" ::: "memory")
#define CP_WAIT0()  asm volatile("cp.async.wait_group 0;" ::: "memory")
#define CP_WAIT1()  asm volatile("cp.async.wait_group 1;" ::: "memory")
#define CP_WAIT_ALL() do { CP_COMMIT(); CP_WAIT0(); } while (0)

__device__ __forceinline__ uint32_t pack2(bf16 a, bf16 b) {
    return (uint32_t)__bfloat16_as_ushort(a) | ((uint32_t)__bfloat16_as_ushort(b) << 16);
}
__device__ __forceinline__ void split_pair(float a, float b, uint32_t& hi, uint32_t& lo) {
    bf16 ha = __float2bfloat16(a), hb = __float2bfloat16(b);
    hi = pack2(ha, hb);
    lo = pack2(__float2bfloat16(a - __bfloat162float(ha)),
               __float2bfloat16(b - __bfloat162float(hb)));
}

// ===========================================================================
// fp32 -> bf16 hi/lo split, all tensors in ONE launch (segment dispatch)
// ===========================================================================
#define SEG0 (MM * DD)
#define SEG1 (SEG0 + DD * DD)
#define SEG2 (SEG1 + DD * DD)
#define SEG3 (SEG2 + DD * DD)
#define SEG4 (SEG3 + DD * DD)
#define SEG5 (SEG4 + NE * HDp)
#define CVT_BLOCKS ((SEG5 / 4 + 255) / 256)

__global__ void cvt_all_kernel(const float* __restrict__ x,  const float* __restrict__ Wq,
                               const float* __restrict__ Wk, const float* __restrict__ Wv,
                               const float* __restrict__ Wo, const float* __restrict__ E)
{
    int i = (blockIdx.x * 256 + threadIdx.x) * 4;
    if (i >= SEG5) return;
    const float* s; bf16 *hi, *lo; int off;
    if      (i < SEG0) { s = x;  hi = g_xhi; lo = g_xlo; off = i; }
    else if (i < SEG1) { s = Wq; hi = g_wqh; lo = g_wql; off = i - SEG0; }
    else if (i < SEG2) { s = Wk; hi = g_wkh; lo = g_wkl; off = i - SEG1; }
    else if (i < SEG3) { s = Wv; hi = g_wvh; lo = g_wvl; off = i - SEG2; }
    else if (i < SEG4) { s = Wo; hi = g_woh; lo = g_wol; off = i - SEG3; }
    else               { s = E;  hi = g_ehi; lo = g_elo; off = i - SEG4; }
    float4 v = *(const float4*)(s + off);
    uint32_t h0, l0, h1, l1;
    split_pair(v.x, v.y, h0, l0);
    split_pair(v.z, v.w, h1, l1);
    *(uint2*)(hi + off) = make_uint2(h0, h1);
    *(uint2*)(lo + off) = make_uint2(l0, l1);
}

// ===========================================================================
// Tensor-core GEMM (R14/R16 proven): C = A(MxK) @ W(NxK)^T + bias.
// 128x128 CTA tile, 512 threads / 16 warps (4m x 4n), warp tile 32x32.
// K chunks of 64, 2-stage cp.async pipeline.
// ===========================================================================
#define GSA     144
#define GTILE_B (128 * GSA)
#define OFF_AHI 0
#define OFF_ALO GTILE_B
#define OFF_BHI (2 * GTILE_B)
#define OFF_BLO (3 * GTILE_B)
#define GBUF_B  (4 * GTILE_B)            // 73728 per stage
#define GEMM_SMEM (2 * GBUF_B)           // 147456

__global__ __launch_bounds__(512, 1)
void gemm_tc2_kernel(const bf16* __restrict__ ahi, const bf16* __restrict__ alo,
                     const bf16* __restrict__ w0h, const bf16* __restrict__ w0l,
                     const bf16* __restrict__ w1h, const bf16* __restrict__ w1l,
                     const bf16* __restrict__ w2h, const bf16* __restrict__ w2l,
                     const float* __restrict__ b0, const float* __restrict__ b1,
                     const float* __restrict__ b2,
                     bf16* c0h, bf16* c0l, bf16* c1h, bf16* c1l,
                     bf16* c2h, bf16* c2l,
                     float* cf, float scale0, int M, int N, int K)
{
    const int z = blockIdx.z;
    const bf16* wh   = (z == 0) ? w0h : (z == 1 ? w1h : w2h);
    const bf16* wl   = (z == 0) ? w0l : (z == 1 ? w1l : w2l);
    const float* bias = (z == 0) ? b0 : (z == 1 ? b1 : b2);
    bf16* chi = (z == 0) ? c0h : (z == 1 ? c1h : c2h);
    bf16* clo = (z == 0) ? c0l : (z == 1 ? c1l : c2l);
    const float scale = (z == 0) ? scale0 : 1.0f;

    extern __shared__ char sm[];
    const uint32_t sbase = smem_u32(sm);

    const int tid  = threadIdx.x;
    const int lane = tid & 31;
    const int wid  = tid >> 5;
    const int wm   = wid & 3;            // 0..3  (32 rows each)
    const int wn   = wid >> 2;           // 0..3  (32 cols each)
    const int bm   = blockIdx.y * 128;
    const int bn   = blockIdx.x * 128;

    float acc[2][4][4];
    #pragma unroll
    for (int i = 0; i < 2; i++)
        #pragma unroll
        for (int j = 0; j < 4; j++)
            #pragma unroll
            for (int r = 0; r < 4; r++) acc[i][j][r] = 0.f;

    const int frow = tid >> 2;
    const int fcol = (tid & 3) * 16;
    const bf16* pah = ahi + (size_t)(bm + frow) * K + fcol;
    const bf16* pal = alo + (size_t)(bm + frow) * K + fcol;
    const bf16* pwh = wh  + (size_t)(bn + frow) * K + fcol;
    const bf16* pwl = wl  + (size_t)(bn + frow) * K + fcol;
    const uint32_t dstrow = (uint32_t)(frow * GSA + fcol * 2);

    const int lr   = lane & 15;
    const int lc16 = (lane >> 4) * 16;
    const uint32_t a_rel = (uint32_t)((wm * 32 + lr) * GSA + lc16);
    const uint32_t b_rel = (uint32_t)((wn * 32 + lr) * GSA + lc16);

    // prologue: issue chunk 0 into buffer 0
    {
        const uint32_t d = sbase + dstrow;
        #pragma unroll
        for (int g = 0; g < 2; g++) {
            cp16(d + OFF_AHI + g * 16, pah + g * 8);
            cp16(d + OFF_ALO + g * 16, pal + g * 8);
            cp16(d + OFF_BHI + g * 16, pwh + g * 8);
            cp16(d + OFF_BLO + g * 16, pwl + g * 8);
        }
        CP_COMMIT();
    }

    const int NCH = K / 64;
    for (int c = 0; c < NCH; c++) {
        if (c + 1 < NCH) {
            const int kb = (c + 1) * 64;
            const uint32_t d = sbase + ((c + 1) & 1) * GBUF_B + dstrow;
            #pragma unroll
            for (int g = 0; g < 2; g++) {
                cp16(d + OFF_AHI + g * 16, pah + kb + g * 8);
                cp16(d + OFF_ALO + g * 16, pal + kb + g * 8);
                cp16(d + OFF_BHI + g * 16, pwh + kb + g * 8);
                cp16(d + OFF_BLO + g * 16, pwl + kb + g * 8);
            }
            CP_COMMIT();
            CP_WAIT1();      // chunk c complete (c+1 still in flight)
        } else {
            CP_WAIT0();
        }
        __syncthreads();     // chunk c visible to all warps

        const uint32_t a_lane = sbase + (c & 1) * GBUF_B + a_rel;
        const uint32_t b_lane = sbase + (c & 1) * GBUF_B + b_rel;
        #pragma unroll
        for (int ks = 0; ks < 4; ks++) {
            const uint32_t cb = (uint32_t)(ks * 32);
            uint32_t ah[2][4], al[2][4];
            #pragma unroll
            for (int mi = 0; mi < 2; mi++) {
                ldsm_x4(a_lane + OFF_AHI + mi * (16 * GSA) + cb, ah[mi]);
                ldsm_x4(a_lane + OFF_ALO + mi * (16 * GSA) + cb, al[mi]);
            }
            uint32_t bh[2][4], bl[2][4];
            #pragma unroll
            for (int nb = 0; nb < 2; nb++) {
                ldsm_x4(b_lane + OFF_BHI + nb * (16 * GSA) + cb, bh[nb]);
                ldsm_x4(b_lane + OFF_BLO + nb * (16 * GSA) + cb, bl[nb]);
            }
            #pragma unroll
            for (int mi = 0; mi < 2; mi++)
                #pragma unroll
                for (int nb = 0; nb < 2; nb++) {
                    mma_bf16(acc[mi][2*nb],   ah[mi], bh[nb][0], bh[nb][2]);
                    mma_bf16(acc[mi][2*nb],   ah[mi], bl[nb][0], bl[nb][2]);
                    mma_bf16(acc[mi][2*nb],   al[mi], bh[nb][0], bh[nb][2]);
                    mma_bf16(acc[mi][2*nb+1], ah[mi], bh[nb][1], bh[nb][3]);
                    mma_bf16(acc[mi][2*nb+1], ah[mi], bl[nb][1], bl[nb][3]);
                    mma_bf16(acc[mi][2*nb+1], al[mi], bh[nb][1], bh[nb][3]);
                }
        }
        __syncthreads();     // all warps done with buffer (c&1) before reuse
    }

    const int ql = lane >> 2;
    const int rl = (lane & 3) * 2;
    #pragma unroll
    for (int mi = 0; mi < 2; mi++) {
        const int m = bm + wm * 32 + mi * 16 + ql;
        #pragma unroll
        for (int nj = 0; nj < 4; nj++) {
            const int n = bn + wn * 32 + nj * 8 + rl;
            const float bz0 = bias[n], bz1 = bias[n + 1];
            if (cf) {
                float2 v;
                v.x = acc[mi][nj][0] + bz0; v.y = acc[mi][nj][1] + bz1;
                *(float2*)(cf + (size_t)m * N + n) = v;
                v.x = acc[mi][nj][2] + bz0; v.y = acc[mi][nj][3] + bz1;
                *(float2*)(cf + (size_t)(m + 8) * N + n) = v;
            } else {
                uint32_t h, l;
                split_pair((acc[mi][nj][0] + bz0) * scale,
                           (acc[mi][nj][1] + bz1) * scale, h, l);
                *(uint32_t*)(chi + (size_t)m * N + n) = h;
                *(uint32_t*)(clo + (size_t)m * N + n) = l;
                split_pair((acc[mi][nj][2] + bz0) * scale,
                           (acc[mi][nj][3] + bz1) * scale, h, l);
                *(uint32_t*)(chi + (size_t)(m + 8) * N + n) = h;
                *(uint32_t*)(clo + (size_t)(m + 8) * N + n) = l;
            }
        }
    }
}

// ===========================================================================
// Tensor-core flash attention, SPLIT-KEY (R12 proven) + CIRCULAR E BUFFER.
// Warp (wr, gj): wr = wid&7 owns q-rows [16wr,16wr+16); gj = wid>>3 owns
// key half [64gj, 64gj+64). Exact online softmax per group; flash merge.
// Band eb range per warp: [7+4gj-wr, 11+4gj-wr].
// E window slides 128 rows (= 8 blocks of 16) per tile: jt=0 loads all 256
// rows; jt>0 loads only the new 128-row half at phys row (li + jt*128)&255.
// Band ldsm uses phys block ebp = (eb + 8*jt) & 15.
// ===========================================================================
#define AKS 144
#define A_KHI 0
#define A_KLO 18432
#define A_VHI 36864
#define A_VLO 55296
#define A_EHI 73728
#define A_ELO 110592
#define A_S   147456
#define ATT_SMEM (A_S + 128 * 132 * 4)    // 215040 B

__global__ __launch_bounds__(512, 1)
void attn_tc_kernel(const bf16* __restrict__ qhi, const bf16* __restrict__ qlo,
                    const bf16* __restrict__ khi, const bf16* __restrict__ klo,
                    const bf16* __restrict__ vhi, const bf16* __restrict__ vlo,
                    const bf16* __restrict__ ehi, const bf16* __restrict__ elo,
                    bf16* __restrict__ chi, bf16* __restrict__ clo)
{
    extern __shared__ char sm[];
    const uint32_t sb = smem_u32(sm);
    float* sS = (float*)(sm + A_S);

    const int tid  = threadIdx.x;
    const int lane = tid & 31;
    const int wid  = tid >> 5;
    const int wr   = wid & 7;            // q-row group
    const int gj   = wid >> 3;           // key half
    const int g    = lane >> 2;
    const int rl   = lane & 3;
    const int i0   = blockIdx.x * 128;
    const int h    = blockIdx.y;
    const int b    = blockIdx.z;
    const size_t tokq = (size_t)(b * LL + i0);

    // ---- stage Q (hi/lo) into S region, grab A-frags ----
    {
        const int r = tid >> 2, ch = (tid & 3) * 16;
        const bf16* ph = qhi + (tokq + r) * DD + h * HDp + ch;
        const bf16* pl = qlo + (tokq + r) * DD + h * HDp + ch;
        const uint32_t dh = sb + A_S + (uint32_t)(r * AKS + ch * 2);
        #pragma unroll
        for (int g2 = 0; g2 < 2; g2++) {
            cp16(dh + g2 * 16,         ph + g2 * 8);
            cp16(dh + 18432 + g2 * 16, pl + g2 * 8);
        }
        CP_WAIT_ALL();
    }
    __syncthreads();
    uint32_t qh[4][4], ql4[4][4];
    {
        const uint32_t aq = sb + A_S + (uint32_t)((wr * 16 + (lane & 15)) * AKS + (lane >> 4) * 16);
        #pragma unroll
        for (int ks = 0; ks < 4; ks++) {
            ldsm_x4(aq + ks * 32, qh[ks]);
            ldsm_x4(aq + 18432 + ks * 32, ql4[ks]);
        }
    }

    float m0 = -1e30f, m1 = -1e30f, den0 = 0.f, den1 = 0.f;
    float o[8][4];
    #pragma unroll
    for (int i = 0; i < 8; i++)
        #pragma unroll
        for (int r = 0; r < 4; r++) o[i][r] = 0.f;

    const int r0 = wr * 16 + g, r1 = r0 + 8;
    const int jlLo = 64 * gj, jlHi = jlLo + 64;
    const int ebLo = 7 + 4 * gj - wr, ebHi = 11 + 4 * gj - wr;

    for (int jt = 0; jt < LL / 128; jt++) {
        const int j0 = jt * 128;
        __syncthreads();   // prior tile's smem reads complete (and Q frags on jt=0)

        // ---- async loads: K hi/lo, V hi/lo (row-major) ----
        {
            const int r = tid >> 2, ch = (tid & 3) * 16;
            const size_t gofs = ((size_t)(b * LL + j0 + r)) * DD + h * HDp + ch;
            const uint32_t drow = (uint32_t)(r * AKS + ch * 2);
            #pragma unroll
            for (int g2 = 0; g2 < 2; g2++) {
                cp16(sb + A_KHI + drow + g2 * 16, khi + gofs + g2 * 8);
                cp16(sb + A_KLO + drow + g2 * 16, klo + gofs + g2 * 8);
                cp16(sb + A_VHI + drow + g2 * 16, vhi + gofs + g2 * 8);
                cp16(sb + A_VLO + drow + g2 * 16, vlo + gofs + g2 * 8);
            }
        }
        // ---- E hi/lo band: full window at jt=0, new half only after ----
        if (jt == 0) {
            const int rb0 = 895 - i0;
            #pragma unroll
            for (int p = 0; p < 4; p++) {
                const int idx = tid + p * 512;
                const int li = idx >> 3, gcol = (idx & 7) * 8;
                const int r = rb0 + li;
                const int rc = (r < 0) ? 0 : r;
                const bool ok = (r >= 0);
                const uint32_t doff = (uint32_t)(li * AKS + gcol * 2);
                cp16z(sb + A_EHI + doff, ehi + (size_t)rc * HDp + gcol, ok);
                cp16z(sb + A_ELO + doff, elo + (size_t)rc * HDp + gcol, ok);
            }
        } else {
            const int rb0 = 895 + j0 - i0;
            #pragma unroll
            for (int p = 0; p < 2; p++) {
                const int idx = tid + p * 512;
                const int li = 128 + (idx >> 3), gcol = (idx & 7) * 8;
                const int r = rb0 + li;                       // always in [0, NE)
                const int phys = (li + jt * 128) & 255;
                const uint32_t doff = (uint32_t)(phys * AKS + gcol * 2);
                cp16(sb + A_EHI + doff, ehi + (size_t)r * HDp + gcol);
                cp16(sb + A_ELO + doff, elo + (size_t)r * HDp + gcol);
            }
        }
        CP_WAIT_ALL();
        __syncthreads();

        // ---- band mma: R = Q . E^T on warp's eb range, scatter to own half ----
        {
            const uint32_t be = sb + A_EHI + (uint32_t)((lane & 15) * AKS + (lane >> 4) * 16);
            const int ebshift = (jt * 8) & 15;
            #pragma unroll
            for (int eb = 0; eb < 16; eb++) {
                if (eb < ebLo || eb > ebHi) continue;
                const int ebp = (eb + ebshift) & 15;
                float ba[2][4] = {{0, 0, 0, 0}, {0, 0, 0, 0}};
                #pragma unroll
                for (int ks = 0; ks < 4; ks++) {
                    uint32_t eh[4], el[4];
                    ldsm_x4(be + ebp * (16 * AKS) + ks * 32, eh);
                    ldsm_x4(be + (A_ELO - A_EHI) + ebp * (16 * AKS) + ks * 32, el);
                    mma_bf16(ba[0], qh[ks],  eh[0], eh[2]);
                    mma_bf16(ba[0], qh[ks],  el[0], el[2]);
                    mma_bf16(ba[0], ql4[ks], eh[0], eh[2]);
                    mma_bf16(ba[1], qh[ks],  eh[1], eh[3]);
                    mma_bf16(ba[1], qh[ks],  el[1], el[3]);
                    mma_bf16(ba[1], ql4[ks], eh[1], eh[3]);
                }
                #pragma unroll
                for (int hf = 0; hf < 2; hf++) {
                    const int li = (eb * 2 + hf) * 8 + rl * 2;
                    int jl;
                    jl = li + r0 - 127;     if (jl >= jlLo && jl < jlHi) sS[r0 * 132 + jl] = ba[hf][0];
                    jl = li + 1 + r0 - 127; if (jl >= jlLo && jl < jlHi) sS[r0 * 132 + jl] = ba[hf][1];
                    jl = li + r1 - 127;     if (jl >= jlLo && jl < jlHi) sS[r1 * 132 + jl] = ba[hf][2];
                    jl = li + 1 + r1 - 127; if (jl >= jlLo && jl < jlHi) sS[r1 * 132 + jl] = ba[hf][3];
                }
            }
        }

        // ---- QK mma on own key half ----
        float acc[8][4];
        #pragma unroll
        for (int i = 0; i < 8; i++)
            #pragma unroll
            for (int r = 0; r < 4; r++) acc[i][r] = 0.f;
        {
            const uint32_t bk = sb + A_KHI + (uint32_t)((lane & 15) * AKS + (lane >> 4) * 16);
            #pragma unroll
            for (int a = 0; a < 4; a++) {
                const int nb = 4 * gj + a;
                #pragma unroll
                for (int ks = 0; ks < 4; ks++) {
                    uint32_t kh[4], kl[4];
                    ldsm_x4(bk + nb * (16 * AKS) + ks * 32, kh);
                    ldsm_x4(bk + (A_KLO - A_KHI) + nb * (16 * AKS) + ks * 32, kl);
                    mma_bf16(acc[2*a],   qh[ks],  kh[0], kh[2]);
                    mma_bf16(acc[2*a],   qh[ks],  kl[0], kl[2]);
                    mma_bf16(acc[2*a],   ql4[ks], kh[0], kh[2]);
                    mma_bf16(acc[2*a+1], qh[ks],  kh[1], kh[3]);
                    mma_bf16(acc[2*a+1], qh[ks],  kl[1], kl[3]);
                    mma_bf16(acc[2*a+1], ql4[ks], kh[1], kh[3]);
                }
            }
        }

        // ---- add band, online softmax over own half ----
        {
            const float* s0 = sS + r0 * 132 + jlLo;
            const float* s1 = sS + r1 * 132 + jlLo;
            #pragma unroll
            for (int nb8 = 0; nb8 < 8; nb8++) {
                const int c = nb8 * 8 + rl * 2;
                acc[nb8][0] += s0[c];     acc[nb8][1] += s0[c + 1];
                acc[nb8][2] += s1[c];     acc[nb8][3] += s1[c + 1];
            }
            float mx0 = -1e30f, mx1 = -1e30f;
            #pragma unroll
            for (int nb8 = 0; nb8 < 8; nb8++) {
                mx0 = fmaxf(mx0, fmaxf(acc[nb8][0], acc[nb8][1]));
                mx1 = fmaxf(mx1, fmaxf(acc[nb8][2], acc[nb8][3]));
            }
            mx0 = fmaxf(mx0, __shfl_xor_sync(0xffffffffu, mx0, 1));
            mx0 = fmaxf(mx0, __shfl_xor_sync(0xffffffffu, mx0, 2));
            mx1 = fmaxf(mx1, __shfl_xor_sync(0xffffffffu, mx1, 1));
            mx1 = fmaxf(mx1, __shfl_xor_sync(0xffffffffu, mx1, 2));
            const float nm0 = fmaxf(m0, mx0), nm1 = fmaxf(m1, mx1);
            const float cr0 = __expf(m0 - nm0), cr1 = __expf(m1 - nm1);
            float s0s = 0.f, s1s = 0.f;
            #pragma unroll
            for (int nb8 = 0; nb8 < 8; nb8++) {
                acc[nb8][0] = __expf(acc[nb8][0] - nm0); s0s += acc[nb8][0];
                acc[nb8][1] = __expf(acc[nb8][1] - nm0); s0s += acc[nb8][1];
                acc[nb8][2] = __expf(acc[nb8][2] - nm1); s1s += acc[nb8][2];
                acc[nb8][3] = __expf(acc[nb8][3] - nm1); s1s += acc[nb8][3];
            }
            s0s += __shfl_xor_sync(0xffffffffu, s0s, 1);
            s0s += __shfl_xor_sync(0xffffffffu, s0s, 2);
            s1s += __shfl_xor_sync(0xffffffffu, s1s, 1);
            s1s += __shfl_xor_sync(0xffffffffu, s1s, 2);
            den0 = den0 * cr0 + s0s; den1 = den1 * cr1 + s1s;
            m0 = nm0; m1 = nm1;
            #pragma unroll
            for (int nd = 0; nd < 8; nd++) {
                o[nd][0] *= cr0; o[nd][1] *= cr0;
                o[nd][2] *= cr1; o[nd][3] *= cr1;
            }
        }

        // ---- PV mma: O += P . V over own key half ----
        {
            const uint32_t bv = sb + A_VHI + (uint32_t)((lane & 15) * AKS + (lane >> 4) * 16);
            #pragma unroll
            for (int kbl = 0; kbl < 4; kbl++) {
                const int kbv = 4 * gj + kbl;
                uint32_t ph4[4], pl4[4];
                split_pair(acc[2*kbl][0],   acc[2*kbl][1],   ph4[0], pl4[0]);
                split_pair(acc[2*kbl][2],   acc[2*kbl][3],   ph4[1], pl4[1]);
                split_pair(acc[2*kbl+1][0], acc[2*kbl+1][1], ph4[2], pl4[2]);
                split_pair(acc[2*kbl+1][2], acc[2*kbl+1][3], ph4[3], pl4[3]);
                #pragma unroll
                for (int dn = 0; dn < 4; dn++) {
                    uint32_t vh[4], vl[4];
                    ldsm_x4t(bv + kbv * (16 * AKS) + dn * 32, vh);
                    ldsm_x4t(bv + (A_VLO - A_VHI) + kbv * (16 * AKS) + dn * 32, vl);
                    mma_bf16(o[2*dn],   ph4, vh[0], vh[1]);
                    mma_bf16(o[2*dn],   ph4, vl[0], vl[1]);
                    mma_bf16(o[2*dn],   pl4, vh[0], vh[1]);
                    mma_bf16(o[2*dn+1], ph4, vh[2], vh[3]);
                    mma_bf16(o[2*dn+1], ph4, vl[2], vl[3]);
                    mma_bf16(o[2*dn+1], pl4, vh[2], vh[3]);
                }
            }
        }
    }

    // ---- epilogue: merge the two key-half groups, normalize, store ----
    __syncthreads();               // all sS reads done; reuse sS for exchange
    {
        float* ex = sS;
        const int slot = (wr * 32 + lane) * 37;
        if (gj == 1) {
            ex[slot + 0] = m0; ex[slot + 1] = m1;
            ex[slot + 2] = den0; ex[slot + 3] = den1;
            #pragma unroll
            for (int nd = 0; nd < 8; nd++)
                #pragma unroll
                for (int r = 0; r < 4; r++)
                    ex[slot + 4 + nd * 4 + r] = o[nd][r];
        }
        __syncthreads();
        if (gj == 0) {
            const float mB0 = ex[slot + 0], mB1 = ex[slot + 1];
            const float dB0 = ex[slot + 2], dB1 = ex[slot + 3];
            const float M0 = fmaxf(m0, mB0), M1 = fmaxf(m1, mB1);
            const float sA0 = __expf(m0 - M0), sB0 = __expf(mB0 - M0);
            const float sA1 = __expf(m1 - M1), sB1 = __expf(mB1 - M1);
            const float inv0 = 1.f / (den0 * sA0 + dB0 * sB0);
            const float inv1 = 1.f / (den1 * sA1 + dB1 * sB1);
            const size_t t0 = tokq + r0, t1 = tokq + r1;
            #pragma unroll
            for (int nd = 0; nd < 8; nd++) {
                const int d = nd * 8 + rl * 2;
                const float* ob = ex + slot + 4 + nd * 4;
                uint32_t hw, lw;
                split_pair((o[nd][0] * sA0 + ob[0] * sB0) * inv0,
                           (o[nd][1] * sA0 + ob[1] * sB0) * inv0, hw, lw);
                *(uint32_t*)(chi + t0 * DD + h * HDp + d) = hw;
                *(uint32_t*)(clo + t0 * DD + h * HDp + d) = lw;
                split_pair((o[nd][2] * sA1 + ob[2] * sB1) * inv1,
                           (o[nd][3] * sA1 + ob[3] * sB1) * inv1, hw, lw);
                *(uint32_t*)(chi + t1 * DD + h * HDp + d) = hw;
                *(uint32_t*)(clo + t1 * DD + h * HDp + d) = lw;
            }
        }
    }
}

// ---------------------------------------------------------------------------
extern "C" void kernel_launch(void* const* d_in, const int* in_sizes, int n_in,
                              void* d_out, int out_size)
{
    const float* x  = (const float*)d_in[0];
    const float* Wq = (const float*)d_in[1];
    const float* bq = (const float*)d_in[2];
    const float* Wk = (const float*)d_in[3];
    const float* bk = (const float*)d_in[4];
    const float* Wv = (const float*)d_in[5];
    const float* bv = (const float*)d_in[6];
    const float* Wo = (const float*)d_in[7];
    const float* bo = (const float*)d_in[8];
    const float* E  = (const float*)d_in[9];
    float* out = (float*)d_out;

    bf16 *xhi, *xlo, *wqh, *wql, *wkh, *wkl, *wvh, *wvl, *woh, *wol;
    bf16 *qhi, *qlo, *khi, *klo, *vhi, *vlo, *ehi, *elo, *chi, *clo;
    cudaGetSymbolAddress((void**)&xhi, g_xhi); cudaGetSymbolAddress((void**)&xlo, g_xlo);
    cudaGetSymbolAddress((void**)&wqh, g_wqh); cudaGetSymbolAddress((void**)&wql, g_wql);
    cudaGetSymbolAddress((void**)&wkh, g_wkh); cudaGetSymbolAddress((void**)&wkl, g_wkl);
    cudaGetSymbolAddress((void**)&wvh, g_wvh); cudaGetSymbolAddress((void**)&wvl, g_wvl);
    cudaGetSymbolAddress((void**)&woh, g_woh); cudaGetSymbolAddress((void**)&wol, g_wol);
    cudaGetSymbolAddress((void**)&qhi, g_qhi); cudaGetSymbolAddress((void**)&qlo, g_qlo);
    cudaGetSymbolAddress((void**)&khi, g_khi); cudaGetSymbolAddress((void**)&klo, g_klo);
    cudaGetSymbolAddress((void**)&vhi, g_vhi); cudaGetSymbolAddress((void**)&vlo, g_vlo);
    cudaGetSymbolAddress((void**)&ehi, g_ehi); cudaGetSymbolAddress((void**)&elo, g_elo);
    cudaGetSymbolAddress((void**)&chi, g_chi); cudaGetSymbolAddress((void**)&clo, g_clo);

    cudaFuncSetAttribute(gemm_tc2_kernel,
                         cudaFuncAttributeMaxDynamicSharedMemorySize, GEMM_SMEM);
    cudaFuncSetAttribute(attn_tc_kernel,
                         cudaFuncAttributeMaxDynamicSharedMemorySize, ATT_SMEM);

    // 0) split all inputs into bf16 hi/lo (single launch)
    cvt_all_kernel<<<CVT_BLOCKS, 256>>>(x, Wq, Wk, Wv, Wo, E);

    // 1) fused QKV projections -> bf16 hi/lo q(scaled), k, v
    gemm_tc2_kernel<<<dim3(DD / 128, MM / 128, 3), 512, GEMM_SMEM>>>(
        xhi, xlo, wqh, wql, wkh, wkl, wvh, wvl, bq, bk, bv,
        qhi, qlo, khi, klo, vhi, vlo, nullptr, 0.125f, MM, DD, DD);

    // 2) tensor-core flash attention with rel-pos band (split-key, circular E)
    attn_tc_kernel<<<dim3(LL / 128, HH, Bb), 512, ATT_SMEM>>>(
        qhi, qlo, khi, klo, vhi, vlo, ehi, elo, chi, clo);

    // 3) output projection -> fp32 out
    gemm_tc2_kernel<<<dim3(DD / 128, MM / 128, 1), 512, GEMM_SMEM>>>(
        chi, clo, woh, wol, woh, wol, woh, wol, bo, bo, bo,
        nullptr, nullptr, nullptr, nullptr, nullptr, nullptr,
        out, 1.0f, MM, DD, DD);
}